// round 14
// baseline (speedup 1.0000x reference)
#include <cuda_runtime.h>
#include <cuda_bf16.h>
#include <cuda_fp16.h>
#include <stdint.h>
#include <math.h>

#define SQ   4096
#define NH   8
#define HD   128
#define EMB  1024
#define NT   32
#define TPK  8
#define NEGV (-1e10f)

// ---------------- scratch (static device globals; no allocs allowed) --------
__device__ float g_tile[NH * NT * NT];
__device__ float g_repm[NH * NT];
__device__ float g_repl[NH * NT];
__device__ __half g_xh[SQ * EMB];
__device__ __half g_xl[SQ * EMB];
__device__ __half g_wth[4 * EMB * EMB];   // [w][n][k] transposed, fp16 hi
__device__ __half g_wtl[4 * EMB * EMB];   // fp16 lo (used only for wq,wk)
__device__ __half g_ah[SQ * EMB];
__device__ __half g_al[SQ * EMB];
__device__ __nv_bfloat16 g_qh[NH * SQ * HD];
__device__ __nv_bfloat16 g_ql[NH * SQ * HD];
__device__ __nv_bfloat16 g_kh[NH * SQ * HD];
__device__ __nv_bfloat16 g_kl[NH * SQ * HD];
__device__ __half g_vh[NH * SQ * HD];

// ======================= helpers ===========================================
__device__ __forceinline__ uint32_t smem_u32(const void* p) {
    uint32_t a;
    asm("{ .reg .u64 t; cvta.to.shared.u64 t, %1; cvt.u32.u64 %0, t; }"
        : "=r"(a) : "l"(p));
    return a;
}
#define SWZ64(o)  ((o) ^ (((o) >> 3) & 0x30))   // 64B rows
#define SWZ256(o) ((o) ^ (((o) >> 4) & 0x70))   // 256B rows

__device__ __forceinline__ void cp16(uint32_t dst, const void* src) {
    asm volatile("cp.async.cg.shared.global [%0], [%1], 16;"
                 :: "r"(dst), "l"(src));
}
__device__ __forceinline__ void cp_commit() {
    asm volatile("cp.async.commit_group;" ::: "memory");
}
__device__ __forceinline__ void cp_wait1() {
    asm volatile("cp.async.wait_group 1;" ::: "memory");
}
__device__ __forceinline__ void cp_wait2() {
    asm volatile("cp.async.wait_group 2;" ::: "memory");
}
__device__ __forceinline__ void cp_wait0() {
    asm volatile("cp.async.wait_group 0;" ::: "memory");
}
__device__ __forceinline__ void ldmx4(uint32_t* r, uint32_t addr) {
    asm volatile("ldmatrix.sync.aligned.m8n8.x4.shared.b16 {%0,%1,%2,%3}, [%4];"
        : "=r"(r[0]), "=r"(r[1]), "=r"(r[2]), "=r"(r[3]) : "r"(addr));
}
__device__ __forceinline__ void ldmx4t(uint32_t* r, uint32_t addr) {
    asm volatile("ldmatrix.sync.aligned.m8n8.x4.trans.shared.b16 {%0,%1,%2,%3}, [%4];"
        : "=r"(r[0]), "=r"(r[1]), "=r"(r[2]), "=r"(r[3]) : "r"(addr));
}
__device__ __forceinline__ void mma16816(float* c, const uint32_t* a,
                                         const uint32_t* b) {
    asm volatile(
        "mma.sync.aligned.m16n8k16.row.col.f32.bf16.bf16.f32 "
        "{%0,%1,%2,%3}, {%4,%5,%6,%7}, {%8,%9}, {%0,%1,%2,%3};"
        : "+f"(c[0]), "+f"(c[1]), "+f"(c[2]), "+f"(c[3])
        : "r"(a[0]), "r"(a[1]), "r"(a[2]), "r"(a[3]), "r"(b[0]), "r"(b[1]));
}
__device__ __forceinline__ void mma16816h(float* c, const uint32_t* a,
                                          const uint32_t* b) {
    asm volatile(
        "mma.sync.aligned.m16n8k16.row.col.f32.f16.f16.f32 "
        "{%0,%1,%2,%3}, {%4,%5,%6,%7}, {%8,%9}, {%0,%1,%2,%3};"
        : "+f"(c[0]), "+f"(c[1]), "+f"(c[2]), "+f"(c[3])
        : "r"(a[0]), "r"(a[1]), "r"(a[2]), "r"(a[3]), "r"(b[0]), "r"(b[1]));
}
__device__ __forceinline__ uint32_t hpack(float lo, float hi) {
    __half2 v = __floats2half2_rn(lo, hi);
    return *reinterpret_cast<uint32_t*>(&v);
}

// ======================= prep kernels =======================================
__global__ void split_kernel(const float* __restrict__ in,
                             __half* __restrict__ hi,
                             __half* __restrict__ lo, int n) {
    int i = blockIdx.x * blockDim.x + threadIdx.x;
    if (i >= n) return;
    float x = in[i];
    __half h = __float2half_rn(x);
    hi[i] = h;
    lo[i] = __float2half_rn(x - __half2float(h));
}

__global__ void wprep_kernel(const float* __restrict__ w0, const float* __restrict__ w1,
                             const float* __restrict__ w2, const float* __restrict__ w3,
                             __half* __restrict__ hi, __half* __restrict__ lo) {
    __shared__ float t[32][33];
    const float* w = (blockIdx.z == 0) ? w0 : (blockIdx.z == 1) ? w1
                    : (blockIdx.z == 2) ? w2 : w3;
    int k0 = blockIdx.x * 32, n0 = blockIdx.y * 32;
    int tx = threadIdx.x, ty = threadIdx.y;
    for (int r = ty; r < 32; r += 8)
        t[r][tx] = w[(size_t)(k0 + r) * EMB + n0 + tx];
    __syncthreads();
    size_t base = (size_t)blockIdx.z * EMB * EMB;
    for (int r = ty; r < 32; r += 8) {
        float x = t[tx][r];
        __half h = __float2half_rn(x);
        size_t o = base + (size_t)(n0 + r) * EMB + k0 + tx;
        hi[o] = h;
        lo[o] = __float2half_rn(x - __half2float(h));
    }
}

// ======================= HMMA GEMM (3-stage cp.async, BK=32, fp16) ==========
// modes: 0 = fp32 row-major out (2-term);
//        3 = combined QKV: z=0 q (3-term, rope+split fused),
//            z=1 k (3-term, rope+split fused), z=2 v (2-term, fp16 head-major)
#define G_STAGE 32768
#define G_SMEM  (3 * G_STAGE)

__global__ __launch_bounds__(256, 2) void gemm_tc(
    const __half* __restrict__ Ah, const __half* __restrict__ Al,
    const __half* __restrict__ Bh, const __half* __restrict__ Bl,
    const float* __restrict__ cosb, const float* __restrict__ sinb,
    float* __restrict__ C, int mode) {
    extern __shared__ __align__(1024) char smem[];
    uint32_t sb = smem_u32(smem);

    int tid = threadIdx.x, wid = tid >> 5, lid = tid & 31;
    int wm = wid & 3, wn = wid >> 2;
    int bm = blockIdx.y * 128, bn = blockIdx.x * 128;
    bool t3 = false;        // 3-term?
    if (mode == 3) {
        size_t zofs = (size_t)blockIdx.z * EMB * EMB;
        Bh += zofs; Bl += zofs;
        t3 = (blockIdx.z < 2);
    }

    float acc[2][8][4];
    #pragma unroll
    for (int i = 0; i < 2; i++)
        #pragma unroll
        for (int j = 0; j < 8; j++)
            #pragma unroll
            for (int kq = 0; kq < 4; kq++) acc[i][j][kq] = 0.0f;

    uint32_t a_row0 = (uint32_t)(wm * 32 + (lid & 15));
    uint32_t a_kb   = (uint32_t)((lid >> 4) * 16);
    uint32_t b_row  = (uint32_t)(wn * 64 + ((lid >> 4) << 3) + (lid & 7));
    uint32_t b_half = (uint32_t)(((lid >> 3) & 1) * 16);

    auto issue = [&](int c, int stg) {
        uint32_t base = sb + stg * G_STAGE;
        #pragma unroll
        for (int it = 0; it < 2; it++) {
            int i = tid + it * 256;
            int r = i >> 2, u = i & 3;
            uint32_t so = SWZ64((uint32_t)(r * 64 + u * 16));
            size_t ga = (size_t)(bm + r) * EMB + c * 32 + u * 8;
            size_t gb = (size_t)(bn + r) * EMB + c * 32 + u * 8;
            cp16(base + so,          Ah + ga);
            cp16(base + 8192 + so,   Al + ga);
            cp16(base + 16384 + so,  Bh + gb);
            if (t3) cp16(base + 24576 + so, Bl + gb);
        }
    };

    issue(0, 0); cp_commit();
    issue(1, 1); cp_commit();
    issue(2, 2); cp_commit();

    int stg = 0;
    for (int c = 0; c < 32; c++) {
        cp_wait2();
        __syncthreads();
        uint32_t saH = sb + stg * G_STAGE;
        uint32_t saL = saH + 8192;
        uint32_t sbH = saH + 16384;
        uint32_t sbL = saH + 24576;
        #pragma unroll
        for (int ks = 0; ks < 2; ks++) {
            uint32_t kofs = (uint32_t)(ks * 32);
            uint32_t aH[2][4], aL[2][4];
            uint32_t o0 = SWZ64(a_row0 * 64 + kofs + a_kb);
            uint32_t o1 = SWZ64((a_row0 + 16) * 64 + kofs + a_kb);
            ldmx4(aH[0], saH + o0);
            ldmx4(aH[1], saH + o1);
            ldmx4(aL[0], saL + o0);
            ldmx4(aL[1], saL + o1);
            #pragma unroll
            for (int pg = 0; pg < 4; pg++) {
                uint32_t bo = SWZ64((b_row + pg * 16) * 64 + kofs + b_half);
                uint32_t bH[4], bL[4];
                ldmx4(bH, sbH + bo);
                if (t3) ldmx4(bL, sbL + bo);
                #pragma unroll
                for (int mt = 0; mt < 2; mt++)
                    #pragma unroll
                    for (int nt = 0; nt < 2; nt++) {
                        float* cc = acc[mt][pg * 2 + nt];
                        mma16816h(cc, aH[mt], bH + nt * 2);
                        if (t3) mma16816h(cc, aH[mt], bL + nt * 2);
                        mma16816h(cc, aL[mt], bH + nt * 2);
                    }
            }
        }
        __syncthreads();
        if (c + 3 < 32) issue(c + 3, stg);
        cp_commit();
        stg = (stg == 2) ? 0 : stg + 1;
    }

    int gr = lid >> 2, gc = (lid & 3) * 2;
    int z = (mode == 3) ? blockIdx.z : -1;

    if (z == 0 || z == 1) {
        // ---- fused rope + bf16 split epilogue (pairs d, d+64 are CTA-local) --
        cp_wait0();
        __syncthreads();
        float* Cst = (float*)smem;            // 128 x 129 fp32 = 66048 B
        #pragma unroll
        for (int mt = 0; mt < 2; mt++) {
            int r0 = wm * 32 + mt * 16 + gr;
            #pragma unroll
            for (int nt = 0; nt < 8; nt++) {
                int col = wn * 64 + nt * 8 + gc;
                Cst[r0 * 129 + col]           = acc[mt][nt][0];
                Cst[r0 * 129 + col + 1]       = acc[mt][nt][1];
                Cst[(r0 + 8) * 129 + col]     = acc[mt][nt][2];
                Cst[(r0 + 8) * 129 + col + 1] = acc[mt][nt][3];
            }
        }
        __syncthreads();
        int head = blockIdx.x;
        const float sc = (z == 0) ? 0.08838834764831845f : 1.0f;
        __nv_bfloat16* oh = (z == 0) ? g_qh : g_kh;
        __nv_bfloat16* ol = (z == 0) ? g_ql : g_kl;
        for (int i = tid; i < 8192; i += 256) {
            int r = i >> 6, d = i & 63;
            float cv = cosb[(bm + r) * 64 + d];
            float sv = sinb[(bm + r) * 64 + d];
            float a = Cst[r * 129 + d];
            float b = Cst[r * 129 + d + 64];
            float y0 = (a * cv - b * sv) * sc;
            float y1 = (b * cv + a * sv) * sc;
            size_t base = ((size_t)head * SQ + bm + r) * 128;
            __nv_bfloat16 t0 = __float2bfloat16(y0);
            __nv_bfloat16 t1 = __float2bfloat16(y1);
            oh[base + d]      = t0;
            ol[base + d]      = __float2bfloat16(y0 - __bfloat162float(t0));
            oh[base + d + 64] = t1;
            ol[base + d + 64] = __float2bfloat16(y1 - __bfloat162float(t1));
        }
        return;
    }

    #pragma unroll
    for (int mt = 0; mt < 2; mt++) {
        int row0 = bm + wm * 32 + mt * 16 + gr;
        #pragma unroll
        for (int nt = 0; nt < 8; nt++) {
            int col = wn * 64 + nt * 8 + gc;
            float v0 = acc[mt][nt][0], v1 = acc[mt][nt][1];
            float v2 = acc[mt][nt][2], v3 = acc[mt][nt][3];
            if (mode == 0) {
                *(float2*)&C[(size_t)row0 * EMB + bn + col] = make_float2(v0, v1);
                *(float2*)&C[(size_t)(row0 + 8) * EMB + bn + col] = make_float2(v2, v3);
            } else {   // z == 2 : v fp16 single, head-major
                size_t hb = ((size_t)(bn >> 7) * SQ) * 128;
                *(uint32_t*)&g_vh[hb + (size_t)row0 * 128 + col] = hpack(v0, v1);
                *(uint32_t*)&g_vh[hb + (size_t)(row0 + 8) * 128 + col] = hpack(v2, v3);
            }
        }
    }
}

// ============ flash attention: BQ=64, BK=32, 128 thr, 2 CTAs/SM =============
// 4 warps x 16 rows, each warp owns the full K-width of its rows (no cross-
// warp reductions). QK bf16 3-term (index-critical); PV fp16 1-term.
#define SM_QH   0
#define SM_QL   16384
#define SM_TMX  32768           // float[32]
#define SM_KV   32896
#define A_STAGE 24576           // kh 8K + kl 8K + vh 8K
#define ATT_SMEM (SM_KV + 2 * A_STAGE)

__global__ __launch_bounds__(128, 2) void attn_tc(
    __half* __restrict__ ah, __half* __restrict__ al) {
    extern __shared__ __align__(1024) char sm[];
    uint32_t sbase = smem_u32(sm);
    uint32_t uQh = sbase + SM_QH, uQl = sbase + SM_QL;
    float* tmax_s = (float*)(sm + SM_TMX);
    uint32_t uKV = sbase + SM_KV;

    int qb = 63 - blockIdx.x;      // heavy tiles first
    int h = blockIdx.y;
    int tid = threadIdx.x, wid = tid >> 5, lid = tid & 31;
    int gr = lid >> 2, qc = lid & 3;

    // load Q hi/lo (64x128 bf16 each, 256B rows SW256)
    {
        const __nv_bfloat16* qh = g_qh + ((size_t)h * SQ + qb * 64) * 128;
        const __nv_bfloat16* ql = g_ql + ((size_t)h * SQ + qb * 64) * 128;
        for (int i = tid; i < 1024; i += 128) {
            int r = i >> 4, ch = i & 15;
            uint32_t so = SWZ256((uint32_t)(r * 256 + ch * 16));
            *(uint4*)(sm + SM_QH + so) = *(const uint4*)(qh + r * 128 + ch * 8);
            *(uint4*)(sm + SM_QL + so) = *(const uint4*)(ql + r * 128 + ch * 8);
        }
    }
    if (tid < 32) tmax_s[tid] = -1e30f;

    float o[16][4];
    #pragma unroll
    for (int j = 0; j < 16; j++)
        #pragma unroll
        for (int i = 0; i < 4; i++) o[j][i] = 0.0f;
    float m0 = -1e30f, m1 = -1e30f, l0 = 0.0f, l1 = 0.0f;

    int row0 = qb * 64 + wid * 16 + gr;
    int row1 = row0 + 8;

    uint32_t qa_row = (uint32_t)(wid * 16 + (lid & 15));
    uint32_t qa_kb  = (uint32_t)((lid >> 4) * 16);
    uint32_t kb_row = (uint32_t)(((lid >> 4) << 3) + (lid & 7));
    uint32_t kb_hf  = (uint32_t)(((lid >> 3) & 1) * 16);
    uint32_t v_row  = (uint32_t)(((lid >> 3) & 1) * 8 + (lid & 7));
    uint32_t v_col  = (uint32_t)((lid >> 4) << 4);

    int nkb = 2 * qb + 2;

    // KV chunk loader: kh/kl/vh 32 rows x 16 16B-units each; 12 cp16/thread
    auto issue = [&](int kb, int stg) {
        uint32_t base = uKV + stg * A_STAGE;
        size_t gb = ((size_t)h * SQ + kb * 32) * 128;
        #pragma unroll
        for (int it = 0; it < 4; it++) {
            int i = tid + it * 128;            // 0..511
            int r = i >> 4, u = i & 15;
            uint32_t so = SWZ256((uint32_t)(r * 256 + u * 16));
            size_t go = gb + r * 128 + u * 8;
            cp16(base + so,          g_kh + go);
            cp16(base + 8192 + so,   g_kl + go);
            cp16(base + 16384 + so,  g_vh + go);
        }
    };

    issue(0, 0); cp_commit();
    issue(1, 1); cp_commit();

    for (int kb = 0; kb < nkb; kb++) {
        int stg = kb & 1;
        cp_wait1();
        __syncthreads();
        uint32_t uKh = uKV + stg * A_STAGE;
        uint32_t uKl = uKh + 8192;
        uint32_t uVh = uKh + 16384;

        // ---- S = Q K^T (bf16 3-term), warp: 16 rows x 32 keys ----
        float s[4][4];
        #pragma unroll
        for (int j = 0; j < 4; j++)
            #pragma unroll
            for (int i = 0; i < 4; i++) s[j][i] = 0.0f;

        #pragma unroll
        for (int dc = 0; dc < 8; dc++) {
            uint32_t qo = SWZ256(qa_row * 256 + (uint32_t)(dc * 32) + qa_kb);
            uint32_t aH[4], aL[4];
            ldmx4(aH, uQh + qo);
            ldmx4(aL, uQl + qo);
            #pragma unroll
            for (int nf = 0; nf < 2; nf++) {
                uint32_t ko = SWZ256((kb_row + nf * 16) * 256 + (uint32_t)(dc * 32) + kb_hf);
                uint32_t bH[4], bL[4];
                ldmx4(bH, uKh + ko);
                ldmx4(bL, uKl + ko);
                #pragma unroll
                for (int nt = 0; nt < 2; nt++) {
                    float* cc = s[nf * 2 + nt];
                    mma16816(cc, aH, bH + nt * 2);
                    mma16816(cc, aH, bL + nt * 2);
                    mma16816(cc, aL, bH + nt * 2);
                }
            }
        }
        if (kb >= 2 * qb) {
            #pragma unroll
            for (int j = 0; j < 4; j++) {
                int colb = kb * 32 + j * 8 + 2 * qc;
                if (colb > row0)     s[j][0] = NEGV;
                if (colb + 1 > row0) s[j][1] = NEGV;
                if (colb > row1)     s[j][2] = NEGV;
                if (colb + 1 > row1) s[j][3] = NEGV;
            }
        }
        float tm0 = -1e30f, tm1 = -1e30f;
        #pragma unroll
        for (int j = 0; j < 4; j++) {
            tm0 = fmaxf(tm0, fmaxf(s[j][0], s[j][1]));
            tm1 = fmaxf(tm1, fmaxf(s[j][2], s[j][3]));
        }
        tm0 = fmaxf(tm0, __shfl_xor_sync(0xffffffffu, tm0, 1));
        tm0 = fmaxf(tm0, __shfl_xor_sync(0xffffffffu, tm0, 2));
        tm1 = fmaxf(tm1, __shfl_xor_sync(0xffffffffu, tm1, 1));
        tm1 = fmaxf(tm1, __shfl_xor_sync(0xffffffffu, tm1, 2));
        if ((qb & 1) && wid == 3 && lid == 28)
            tmax_s[kb >> 2] = fmaxf(tmax_s[kb >> 2], tm1);
        float mn0 = fmaxf(m0, tm0), mn1 = fmaxf(m1, tm1);
        float al0 = __expf(m0 - mn0), al1 = __expf(m1 - mn1);
        m0 = mn0; m1 = mn1;
        #pragma unroll
        for (int j = 0; j < 16; j++) {
            o[j][0] *= al0; o[j][1] *= al0;
            o[j][2] *= al1; o[j][3] *= al1;
        }
        float rs0 = 0.0f, rs1 = 0.0f;
        // ---- P (fp16, single) fed into 1-term fp16 PV ----
        #pragma unroll
        for (int t = 0; t < 2; t++) {
            uint32_t pH[4];
            #pragma unroll
            for (int jj = 0; jj < 2; jj++) {
                int j = 2 * t + jj;
                float e0 = __expf(s[j][0] - m0);
                float e1 = __expf(s[j][1] - m0);
                float e2 = __expf(s[j][2] - m1);
                float e3 = __expf(s[j][3] - m1);
                rs0 += e0 + e1; rs1 += e2 + e3;
                pH[2 * jj]     = hpack(e0, e1);
                pH[2 * jj + 1] = hpack(e2, e3);
            }
            #pragma unroll
            for (int nf = 0; nf < 8; nf++) {
                uint32_t vo = SWZ256((uint32_t)((t * 16 + v_row) * 256 + nf * 32) + v_col);
                uint32_t vH[4];
                ldmx4t(vH, uVh + vo);
                #pragma unroll
                for (int nt = 0; nt < 2; nt++)
                    mma16816h(o[nf * 2 + nt], pH, vH + nt * 2);
            }
        }
        rs0 += __shfl_xor_sync(0xffffffffu, rs0, 1);
        rs0 += __shfl_xor_sync(0xffffffffu, rs0, 2);
        rs1 += __shfl_xor_sync(0xffffffffu, rs1, 1);
        rs1 += __shfl_xor_sync(0xffffffffu, rs1, 2);
        l0 = l0 * al0 + rs0;
        l1 = l1 * al1 + rs1;

        __syncthreads();
        if (kb + 2 < nkb) issue(kb + 2, stg);
        cp_commit();
    }

    // ---- epilogue: normalize, split to fp16 hi/lo, write [s][h*128+d] ----
    float inv0 = 1.0f / l0, inv1 = 1.0f / l1;
    #pragma unroll
    for (int j = 0; j < 16; j++) {
        int col = h * 128 + j * 8 + 2 * qc;
        float v0 = o[j][0] * inv0, v1 = o[j][1] * inv0;
        float v2 = o[j][2] * inv1, v3 = o[j][3] * inv1;
        __half h0 = __float2half_rn(v0);
        __half h1 = __float2half_rn(v1);
        __half h2 = __float2half_rn(v2);
        __half h3 = __float2half_rn(v3);
        __half2 p0; p0.x = h0; p0.y = h1;
        __half2 p1; p1.x = h2; p1.y = h3;
        *(uint32_t*)&ah[(size_t)row0 * EMB + col] = *(uint32_t*)&p0;
        *(uint32_t*)&ah[(size_t)row1 * EMB + col] = *(uint32_t*)&p1;
        *(uint32_t*)&al[(size_t)row0 * EMB + col] =
            hpack(v0 - __half2float(h0), v1 - __half2float(h1));
        *(uint32_t*)&al[(size_t)row1 * EMB + col] =
            hpack(v2 - __half2float(h2), v3 - __half2float(h3));
    }
    if ((qb & 1) && wid == 3 && lid == 28) {
        g_repm[h * NT + (qb >> 1)] = m1;
        g_repl[h * NT + (qb >> 1)] = l1;
    }
    __syncthreads();
    if ((qb & 1) && tid < 32)
        g_tile[((size_t)h * NT + (qb >> 1)) * NT + tid] = tmax_s[tid];
}

// ---------------- anchor tile scores + top-8 --------------------------------
__global__ void topk_kernel(float* __restrict__ out) {
    int t = blockIdx.x * blockDim.x + threadIdx.x;
    if (t >= NH * NT) return;
    int qt = t & (NT - 1);
    float m = g_repm[t], l = g_repl[t];
    float sc[NT];
    #pragma unroll
    for (int kt = 0; kt < NT; kt++)
        sc[kt] = (kt <= qt) ? expf(g_tile[(size_t)t * NT + kt] - m) / l : 0.0f;
    float* dst = out + (size_t)SQ * EMB + (size_t)t * TPK;
    for (int r = 0; r < TPK; r++) {
        float bv = -1e38f; int bi = 0;
        #pragma unroll
        for (int kt = 0; kt < NT; kt++)
            if (sc[kt] > bv) { bv = sc[kt]; bi = kt; }
        sc[bi] = -1e38f;
        dst[r] = (float)bi;
    }
}

// ---------------- launch ----------------------------------------------------
extern "C" void kernel_launch(void* const* d_in, const int* in_sizes, int n_in,
                              void* d_out, int out_size) {
    const float* x    = (const float*)d_in[0];
    const float* wq   = (const float*)d_in[1];
    const float* wk   = (const float*)d_in[2];
    const float* wv   = (const float*)d_in[3];
    const float* wo   = (const float*)d_in[4];
    const float* cosb = (const float*)d_in[5];
    const float* sinb = (const float*)d_in[6];
    float* out = (float*)d_out;

    void *pxh, *pxl, *pwth, *pwtl, *pah, *pal;
    cudaGetSymbolAddress(&pxh, g_xh);
    cudaGetSymbolAddress(&pxl, g_xl);
    cudaGetSymbolAddress(&pwth, g_wth);
    cudaGetSymbolAddress(&pwtl, g_wtl);
    cudaGetSymbolAddress(&pah, g_ah);
    cudaGetSymbolAddress(&pal, g_al);
    __half* xh = (__half*)pxh;
    __half* xl = (__half*)pxl;
    __half* wth = (__half*)pwth;
    __half* wtl = (__half*)pwtl;
    __half* ah = (__half*)pah;
    __half* al = (__half*)pal;

    cudaFuncSetAttribute(gemm_tc, cudaFuncAttributeMaxDynamicSharedMemorySize, G_SMEM);
    cudaFuncSetAttribute(attn_tc, cudaFuncAttributeMaxDynamicSharedMemorySize, ATT_SMEM);

    const size_t WSZ = (size_t)EMB * EMB;

    split_kernel<<<(SQ * EMB + 255) / 256, 256>>>(x, xh, xl, SQ * EMB);
    wprep_kernel<<<dim3(32, 32, 4), dim3(32, 8)>>>(wq, wk, wv, wo, wth, wtl);

    // combined QKV (z = 0,1,2); rope fused into z=0/1 epilogue
    gemm_tc<<<dim3(EMB / 128, SQ / 128, 3), 256, G_SMEM>>>(
        xh, xl, wth, wtl, cosb, sinb, nullptr, 3);

    attn_tc<<<dim3(64, NH), 128, ATT_SMEM>>>(ah, al);

    gemm_tc<<<dim3(EMB / 128, SQ / 128), 256, G_SMEM>>>(
        ah, al, wth + 3 * WSZ, wtl + 3 * WSZ, nullptr, nullptr, out, 0);

    if (out_size >= SQ * EMB + NH * NT * TPK)
        topk_kernel<<<1, 256>>>(out);
}

// round 15
// speedup vs baseline: 1.4664x; 1.4664x over previous
#include <cuda_runtime.h>
#include <cuda_bf16.h>
#include <cuda_fp16.h>
#include <stdint.h>
#include <math.h>

#define SQ   4096
#define NH   8
#define HD   128
#define EMB  1024
#define NT   32
#define TPK  8
#define NEGV (-1e10f)

// ---------------- scratch (static device globals; no allocs allowed) --------
__device__ float g_tile[NH * NT * NT];
__device__ float g_repm[NH * NT];
__device__ float g_repl[NH * NT];
__device__ __half g_xh[SQ * EMB];
__device__ __half g_xl[SQ * EMB];
__device__ __half g_wth[4 * EMB * EMB];   // [w][n][k] transposed, fp16 hi
__device__ __half g_wtl[4 * EMB * EMB];   // fp16 lo (used only for wq,wk)
__device__ __half g_ah[SQ * EMB];
__device__ __half g_al[SQ * EMB];
__device__ __nv_bfloat16 g_qh[NH * SQ * HD];
__device__ __nv_bfloat16 g_ql[NH * SQ * HD];
__device__ __nv_bfloat16 g_kh[NH * SQ * HD];
__device__ __nv_bfloat16 g_kl[NH * SQ * HD];
__device__ __half g_vh[NH * SQ * HD];

// ======================= helpers ===========================================
__device__ __forceinline__ uint32_t smem_u32(const void* p) {
    uint32_t a;
    asm("{ .reg .u64 t; cvta.to.shared.u64 t, %1; cvt.u32.u64 %0, t; }"
        : "=r"(a) : "l"(p));
    return a;
}
#define SWZ64(o)  ((o) ^ (((o) >> 3) & 0x30))   // 64B rows
#define SWZ256(o) ((o) ^ (((o) >> 4) & 0x70))   // 256B rows

__device__ __forceinline__ void cp16(uint32_t dst, const void* src) {
    asm volatile("cp.async.cg.shared.global [%0], [%1], 16;"
                 :: "r"(dst), "l"(src));
}
__device__ __forceinline__ void cp_commit() {
    asm volatile("cp.async.commit_group;" ::: "memory");
}
__device__ __forceinline__ void cp_wait1() {
    asm volatile("cp.async.wait_group 1;" ::: "memory");
}
__device__ __forceinline__ void cp_wait2() {
    asm volatile("cp.async.wait_group 2;" ::: "memory");
}
__device__ __forceinline__ void cp_wait0() {
    asm volatile("cp.async.wait_group 0;" ::: "memory");
}
__device__ __forceinline__ void ldmx4(uint32_t* r, uint32_t addr) {
    asm volatile("ldmatrix.sync.aligned.m8n8.x4.shared.b16 {%0,%1,%2,%3}, [%4];"
        : "=r"(r[0]), "=r"(r[1]), "=r"(r[2]), "=r"(r[3]) : "r"(addr));
}
__device__ __forceinline__ void ldmx4t(uint32_t* r, uint32_t addr) {
    asm volatile("ldmatrix.sync.aligned.m8n8.x4.trans.shared.b16 {%0,%1,%2,%3}, [%4];"
        : "=r"(r[0]), "=r"(r[1]), "=r"(r[2]), "=r"(r[3]) : "r"(addr));
}
__device__ __forceinline__ void mma16816(float* c, const uint32_t* a,
                                         const uint32_t* b) {
    asm volatile(
        "mma.sync.aligned.m16n8k16.row.col.f32.bf16.bf16.f32 "
        "{%0,%1,%2,%3}, {%4,%5,%6,%7}, {%8,%9}, {%0,%1,%2,%3};"
        : "+f"(c[0]), "+f"(c[1]), "+f"(c[2]), "+f"(c[3])
        : "r"(a[0]), "r"(a[1]), "r"(a[2]), "r"(a[3]), "r"(b[0]), "r"(b[1]));
}
__device__ __forceinline__ void mma16816h(float* c, const uint32_t* a,
                                          const uint32_t* b) {
    asm volatile(
        "mma.sync.aligned.m16n8k16.row.col.f32.f16.f16.f32 "
        "{%0,%1,%2,%3}, {%4,%5,%6,%7}, {%8,%9}, {%0,%1,%2,%3};"
        : "+f"(c[0]), "+f"(c[1]), "+f"(c[2]), "+f"(c[3])
        : "r"(a[0]), "r"(a[1]), "r"(a[2]), "r"(a[3]), "r"(b[0]), "r"(b[1]));
}
__device__ __forceinline__ uint32_t hpack(float lo, float hi) {
    __half2 v = __floats2half2_rn(lo, hi);
    return *reinterpret_cast<uint32_t*>(&v);
}

// ======================= prep kernels =======================================
__global__ void split_kernel(const float* __restrict__ in,
                             __half* __restrict__ hi,
                             __half* __restrict__ lo, int n) {
    int i = blockIdx.x * blockDim.x + threadIdx.x;
    if (i >= n) return;
    float x = in[i];
    __half h = __float2half_rn(x);
    hi[i] = h;
    lo[i] = __float2half_rn(x - __half2float(h));
}

__global__ void wprep_kernel(const float* __restrict__ w0, const float* __restrict__ w1,
                             const float* __restrict__ w2, const float* __restrict__ w3,
                             __half* __restrict__ hi, __half* __restrict__ lo) {
    __shared__ float t[32][33];
    const float* w = (blockIdx.z == 0) ? w0 : (blockIdx.z == 1) ? w1
                    : (blockIdx.z == 2) ? w2 : w3;
    int k0 = blockIdx.x * 32, n0 = blockIdx.y * 32;
    int tx = threadIdx.x, ty = threadIdx.y;
    for (int r = ty; r < 32; r += 8)
        t[r][tx] = w[(size_t)(k0 + r) * EMB + n0 + tx];
    __syncthreads();
    size_t base = (size_t)blockIdx.z * EMB * EMB;
    for (int r = ty; r < 32; r += 8) {
        float x = t[tx][r];
        __half h = __float2half_rn(x);
        size_t o = base + (size_t)(n0 + r) * EMB + k0 + tx;
        hi[o] = h;
        lo[o] = __float2half_rn(x - __half2float(h));
    }
}

// ======================= HMMA GEMM (3-stage cp.async, BK=32, fp16) ==========
// modes: 0 = fp32 row-major out (2-term);
//        3 = combined QKV: z=0 q (3-term, rope+split fused),
//            z=1 k (3-term, rope+split fused), z=2 v (2-term, fp16 head-major)
#define G_STAGE 32768
#define G_SMEM  (3 * G_STAGE)

__global__ __launch_bounds__(256, 2) void gemm_tc(
    const __half* __restrict__ Ah, const __half* __restrict__ Al,
    const __half* __restrict__ Bh, const __half* __restrict__ Bl,
    const float* __restrict__ cosb, const float* __restrict__ sinb,
    float* __restrict__ C, int mode) {
    extern __shared__ __align__(1024) char smem[];
    uint32_t sb = smem_u32(smem);

    int tid = threadIdx.x, wid = tid >> 5, lid = tid & 31;
    int wm = wid & 3, wn = wid >> 2;
    int bm = blockIdx.y * 128, bn = blockIdx.x * 128;
    bool t3 = false;        // 3-term?
    if (mode == 3) {
        size_t zofs = (size_t)blockIdx.z * EMB * EMB;
        Bh += zofs; Bl += zofs;
        t3 = (blockIdx.z < 2);
    }

    float acc[2][8][4];
    #pragma unroll
    for (int i = 0; i < 2; i++)
        #pragma unroll
        for (int j = 0; j < 8; j++)
            #pragma unroll
            for (int kq = 0; kq < 4; kq++) acc[i][j][kq] = 0.0f;

    uint32_t a_row0 = (uint32_t)(wm * 32 + (lid & 15));
    uint32_t a_kb   = (uint32_t)((lid >> 4) * 16);
    uint32_t b_row  = (uint32_t)(wn * 64 + ((lid >> 4) << 3) + (lid & 7));
    uint32_t b_half = (uint32_t)(((lid >> 3) & 1) * 16);

    auto issue = [&](int c, int stg) {
        uint32_t base = sb + stg * G_STAGE;
        #pragma unroll
        for (int it = 0; it < 2; it++) {
            int i = tid + it * 256;
            int r = i >> 2, u = i & 3;
            uint32_t so = SWZ64((uint32_t)(r * 64 + u * 16));
            size_t ga = (size_t)(bm + r) * EMB + c * 32 + u * 8;
            size_t gb = (size_t)(bn + r) * EMB + c * 32 + u * 8;
            cp16(base + so,          Ah + ga);
            cp16(base + 8192 + so,   Al + ga);
            cp16(base + 16384 + so,  Bh + gb);
            if (t3) cp16(base + 24576 + so, Bl + gb);
        }
    };

    issue(0, 0); cp_commit();
    issue(1, 1); cp_commit();
    issue(2, 2); cp_commit();

    int stg = 0;
    for (int c = 0; c < 32; c++) {
        cp_wait2();
        __syncthreads();
        uint32_t saH = sb + stg * G_STAGE;
        uint32_t saL = saH + 8192;
        uint32_t sbH = saH + 16384;
        uint32_t sbL = saH + 24576;
        #pragma unroll
        for (int ks = 0; ks < 2; ks++) {
            uint32_t kofs = (uint32_t)(ks * 32);
            uint32_t aH[2][4], aL[2][4];
            uint32_t o0 = SWZ64(a_row0 * 64 + kofs + a_kb);
            uint32_t o1 = SWZ64((a_row0 + 16) * 64 + kofs + a_kb);
            ldmx4(aH[0], saH + o0);
            ldmx4(aH[1], saH + o1);
            ldmx4(aL[0], saL + o0);
            ldmx4(aL[1], saL + o1);
            #pragma unroll
            for (int pg = 0; pg < 4; pg++) {
                uint32_t bo = SWZ64((b_row + pg * 16) * 64 + kofs + b_half);
                uint32_t bH[4], bL[4];
                ldmx4(bH, sbH + bo);
                if (t3) ldmx4(bL, sbL + bo);
                #pragma unroll
                for (int mt = 0; mt < 2; mt++)
                    #pragma unroll
                    for (int nt = 0; nt < 2; nt++) {
                        float* cc = acc[mt][pg * 2 + nt];
                        mma16816h(cc, aH[mt], bH + nt * 2);
                        if (t3) mma16816h(cc, aH[mt], bL + nt * 2);
                        mma16816h(cc, aL[mt], bH + nt * 2);
                    }
            }
        }
        __syncthreads();
        if (c + 3 < 32) issue(c + 3, stg);
        cp_commit();
        stg = (stg == 2) ? 0 : stg + 1;
    }

    int gr = lid >> 2, gc = (lid & 3) * 2;
    int z = (mode == 3) ? blockIdx.z : -1;

    if (z == 0 || z == 1) {
        // ---- fused rope + bf16 split epilogue (pairs d, d+64 are CTA-local) --
        cp_wait0();
        __syncthreads();
        float* Cst = (float*)smem;            // 128 x 129 fp32 = 66048 B
        #pragma unroll
        for (int mt = 0; mt < 2; mt++) {
            int r0 = wm * 32 + mt * 16 + gr;
            #pragma unroll
            for (int nt = 0; nt < 8; nt++) {
                int col = wn * 64 + nt * 8 + gc;
                Cst[r0 * 129 + col]           = acc[mt][nt][0];
                Cst[r0 * 129 + col + 1]       = acc[mt][nt][1];
                Cst[(r0 + 8) * 129 + col]     = acc[mt][nt][2];
                Cst[(r0 + 8) * 129 + col + 1] = acc[mt][nt][3];
            }
        }
        __syncthreads();
        int head = blockIdx.x;
        const float sc = (z == 0) ? 0.08838834764831845f : 1.0f;
        __nv_bfloat16* oh = (z == 0) ? g_qh : g_kh;
        __nv_bfloat16* ol = (z == 0) ? g_ql : g_kl;
        for (int i = tid; i < 8192; i += 256) {
            int r = i >> 6, d = i & 63;
            float cv = cosb[(bm + r) * 64 + d];
            float sv = sinb[(bm + r) * 64 + d];
            float a = Cst[r * 129 + d];
            float b = Cst[r * 129 + d + 64];
            float y0 = (a * cv - b * sv) * sc;
            float y1 = (b * cv + a * sv) * sc;
            size_t base = ((size_t)head * SQ + bm + r) * 128;
            __nv_bfloat16 t0 = __float2bfloat16(y0);
            __nv_bfloat16 t1 = __float2bfloat16(y1);
            oh[base + d]      = t0;
            ol[base + d]      = __float2bfloat16(y0 - __bfloat162float(t0));
            oh[base + d + 64] = t1;
            ol[base + d + 64] = __float2bfloat16(y1 - __bfloat162float(t1));
        }
        return;
    }

    #pragma unroll
    for (int mt = 0; mt < 2; mt++) {
        int row0 = bm + wm * 32 + mt * 16 + gr;
        #pragma unroll
        for (int nt = 0; nt < 8; nt++) {
            int col = wn * 64 + nt * 8 + gc;
            float v0 = acc[mt][nt][0], v1 = acc[mt][nt][1];
            float v2 = acc[mt][nt][2], v3 = acc[mt][nt][3];
            if (mode == 0) {
                *(float2*)&C[(size_t)row0 * EMB + bn + col] = make_float2(v0, v1);
                *(float2*)&C[(size_t)(row0 + 8) * EMB + bn + col] = make_float2(v2, v3);
            } else {   // z == 2 : v fp16 single, head-major
                size_t hb = ((size_t)(bn >> 7) * SQ) * 128;
                *(uint32_t*)&g_vh[hb + (size_t)row0 * 128 + col] = hpack(v0, v1);
                *(uint32_t*)&g_vh[hb + (size_t)(row0 + 8) * 128 + col] = hpack(v2, v3);
            }
        }
    }
}

// ============ tensor-core flash attention, BQ=128, BK=64, 3-stage KV ========
// QK: bf16 3-term (index-critical). PV: fp16 1-term. One barrier per iter:
// with 3 KV stages, the write target (kb+2)%3 never aliases the read stage
// kb%3, and the top barrier guarantees stage (kb-1)%3 reads are done.
#define A_STAGE 49152
#define ATT_SMEM (65536 + 3 * A_STAGE + 128)

__global__ __launch_bounds__(256, 1) void attn_tc(
    __half* __restrict__ ah, __half* __restrict__ al) {
    extern __shared__ __align__(1024) char sm[];
    char* sQh = sm;                 // 32KB Qh + 32KB Ql, 256B rows
    char* sQl = sm + 32768;
    float* tmax_s = (float*)(sm + 65536 + 3 * A_STAGE);
    uint32_t uQh = smem_u32(sQh), uQl = smem_u32(sQl);
    uint32_t uKV = smem_u32(sm + 65536);   // stage base

    int qb = (NT - 1) - blockIdx.x;
    int h = blockIdx.y;
    int tid = threadIdx.x, wid = tid >> 5, lid = tid & 31;
    int gr = lid >> 2, qc = lid & 3;

    {
        const __nv_bfloat16* qh = g_qh + ((size_t)h * SQ + qb * 128) * 128;
        const __nv_bfloat16* ql = g_ql + ((size_t)h * SQ + qb * 128) * 128;
        for (int i = tid; i < 2048; i += 256) {
            int r = i >> 4, ch = i & 15;
            uint32_t so = SWZ256((uint32_t)(r * 256 + ch * 16));
            *(uint4*)(sQh + so) = *(const uint4*)(qh + r * 128 + ch * 8);
            *(uint4*)(sQl + so) = *(const uint4*)(ql + r * 128 + ch * 8);
        }
    }
    if (tid < 32) tmax_s[tid] = -1e30f;

    float o[16][4];
    #pragma unroll
    for (int j = 0; j < 16; j++)
        #pragma unroll
        for (int i = 0; i < 4; i++) o[j][i] = 0.0f;
    float m0 = -1e30f, m1 = -1e30f, l0 = 0.0f, l1 = 0.0f;

    int row0 = qb * 128 + wid * 16 + gr;
    int row1 = row0 + 8;

    uint32_t qa_row = (uint32_t)(wid * 16 + (lid & 15));
    uint32_t qa_kb  = (uint32_t)((lid >> 4) * 16);
    uint32_t kb_row = (uint32_t)(((lid >> 4) << 3) + (lid & 7));
    uint32_t kb_hf  = (uint32_t)(((lid >> 3) & 1) * 16);
    uint32_t v_row  = (uint32_t)(((lid >> 3) & 1) * 8 + (lid & 7));
    uint32_t v_col  = (uint32_t)((lid >> 4) << 4);

    int nkb = 2 * qb + 2;

    auto issue = [&](int kb, int stg) {
        uint32_t base = uKV + stg * A_STAGE;
        size_t gb = ((size_t)h * SQ + kb * 64) * 128;
        #pragma unroll
        for (int it = 0; it < 4; it++) {
            int i = tid + it * 256;
            int r = i >> 4, u = i & 15;
            uint32_t so = SWZ256((uint32_t)(r * 256 + u * 16));
            size_t go = gb + r * 128 + u * 8;
            cp16(base + so,          g_kh + go);
            cp16(base + 16384 + so,  g_kl + go);
            cp16(base + 32768 + so,  g_vh + go);
        }
    };

    issue(0, 0); cp_commit();
    issue(1, 1); cp_commit();

    int stg = 0;
    for (int kb = 0; kb < nkb; kb++) {
        cp_wait1();
        __syncthreads();               // single barrier per iteration
        // prefetch kb+2 into a stage disjoint from the one being read
        if (kb + 2 < nkb) issue(kb + 2, (stg + 2) % 3);
        cp_commit();
        uint32_t uKh = uKV + stg * A_STAGE;
        uint32_t uKl = uKh + 16384;
        uint32_t uVh = uKh + 32768;

        // ---- S = Q K^T (bf16 3-term, index-critical) ----
        float s[8][4];
        #pragma unroll
        for (int j = 0; j < 8; j++)
            #pragma unroll
            for (int i = 0; i < 4; i++) s[j][i] = 0.0f;

        #pragma unroll
        for (int dc = 0; dc < 8; dc++) {
            uint32_t qo = SWZ256(qa_row * 256 + (uint32_t)(dc * 32) + qa_kb);
            uint32_t aH[4], aL[4];
            ldmx4(aH, uQh + qo);
            ldmx4(aL, uQl + qo);
            #pragma unroll
            for (int nf = 0; nf < 4; nf++) {
                uint32_t ko = SWZ256((kb_row + nf * 16) * 256 + (uint32_t)(dc * 32) + kb_hf);
                uint32_t bH[4], bL[4];
                ldmx4(bH, uKh + ko);
                ldmx4(bL, uKl + ko);
                #pragma unroll
                for (int nt = 0; nt < 2; nt++) {
                    float* cc = s[nf * 2 + nt];
                    mma16816(cc, aH, bH + nt * 2);
                    mma16816(cc, aH, bL + nt * 2);
                    mma16816(cc, aL, bH + nt * 2);
                }
            }
        }
        if (kb >= 2 * qb) {
            #pragma unroll
            for (int j = 0; j < 8; j++) {
                int colb = kb * 64 + j * 8 + 2 * qc;
                if (colb > row0)     s[j][0] = NEGV;
                if (colb + 1 > row0) s[j][1] = NEGV;
                if (colb > row1)     s[j][2] = NEGV;
                if (colb + 1 > row1) s[j][3] = NEGV;
            }
        }
        float tm0 = -1e30f, tm1 = -1e30f;
        #pragma unroll
        for (int j = 0; j < 8; j++) {
            tm0 = fmaxf(tm0, fmaxf(s[j][0], s[j][1]));
            tm1 = fmaxf(tm1, fmaxf(s[j][2], s[j][3]));
        }
        tm0 = fmaxf(tm0, __shfl_xor_sync(0xffffffffu, tm0, 1));
        tm0 = fmaxf(tm0, __shfl_xor_sync(0xffffffffu, tm0, 2));
        tm1 = fmaxf(tm1, __shfl_xor_sync(0xffffffffu, tm1, 1));
        tm1 = fmaxf(tm1, __shfl_xor_sync(0xffffffffu, tm1, 2));
        if (wid == 7 && lid == 28)
            tmax_s[kb >> 1] = fmaxf(tmax_s[kb >> 1], tm1);
        float mn0 = fmaxf(m0, tm0), mn1 = fmaxf(m1, tm1);
        float al0 = __expf(m0 - mn0), al1 = __expf(m1 - mn1);
        m0 = mn0; m1 = mn1;
        #pragma unroll
        for (int j = 0; j < 16; j++) {
            o[j][0] *= al0; o[j][1] *= al0;
            o[j][2] *= al1; o[j][3] *= al1;
        }
        float rs0 = 0.0f, rs1 = 0.0f;
        // ---- P (fp16, single) fed into 1-term fp16 PV ----
        #pragma unroll
        for (int t = 0; t < 4; t++) {
            uint32_t pH[4];
            #pragma unroll
            for (int jj = 0; jj < 2; jj++) {
                int j = 2 * t + jj;
                float e0 = __expf(s[j][0] - m0);
                float e1 = __expf(s[j][1] - m0);
                float e2 = __expf(s[j][2] - m1);
                float e3 = __expf(s[j][3] - m1);
                rs0 += e0 + e1; rs1 += e2 + e3;
                pH[2 * jj]     = hpack(e0, e1);
                pH[2 * jj + 1] = hpack(e2, e3);
            }
            #pragma unroll
            for (int nf = 0; nf < 8; nf++) {
                uint32_t vo = SWZ256((uint32_t)((t * 16 + v_row) * 256 + nf * 32) + v_col);
                uint32_t vH[4];
                ldmx4t(vH, uVh + vo);
                #pragma unroll
                for (int nt = 0; nt < 2; nt++)
                    mma16816h(o[nf * 2 + nt], pH, vH + nt * 2);
            }
        }
        rs0 += __shfl_xor_sync(0xffffffffu, rs0, 1);
        rs0 += __shfl_xor_sync(0xffffffffu, rs0, 2);
        rs1 += __shfl_xor_sync(0xffffffffu, rs1, 1);
        rs1 += __shfl_xor_sync(0xffffffffu, rs1, 2);
        l0 = l0 * al0 + rs0;
        l1 = l1 * al1 + rs1;

        stg = (stg == 2) ? 0 : stg + 1;
    }

    float inv0 = 1.0f / l0, inv1 = 1.0f / l1;
    #pragma unroll
    for (int j = 0; j < 16; j++) {
        int col = h * 128 + j * 8 + 2 * qc;
        float v0 = o[j][0] * inv0, v1 = o[j][1] * inv0;
        float v2 = o[j][2] * inv1, v3 = o[j][3] * inv1;
        __half h0 = __float2half_rn(v0);
        __half h1 = __float2half_rn(v1);
        __half h2 = __float2half_rn(v2);
        __half h3 = __float2half_rn(v3);
        __half2 p0; p0.x = h0; p0.y = h1;
        __half2 p1; p1.x = h2; p1.y = h3;
        *(uint32_t*)&ah[(size_t)row0 * EMB + col] = *(uint32_t*)&p0;
        *(uint32_t*)&ah[(size_t)row1 * EMB + col] = *(uint32_t*)&p1;
        *(uint32_t*)&al[(size_t)row0 * EMB + col] =
            hpack(v0 - __half2float(h0), v1 - __half2float(h1));
        *(uint32_t*)&al[(size_t)row1 * EMB + col] =
            hpack(v2 - __half2float(h2), v3 - __half2float(h3));
    }
    if (wid == 7 && lid == 28) {
        g_repm[h * NT + qb] = m1;
        g_repl[h * NT + qb] = l1;
    }
    __syncthreads();
    if (tid < 32)
        g_tile[((size_t)h * NT + qb) * NT + tid] = tmax_s[tid];
}

// ---------------- anchor tile scores + top-8 --------------------------------
__global__ void topk_kernel(float* __restrict__ out) {
    int t = blockIdx.x * blockDim.x + threadIdx.x;
    if (t >= NH * NT) return;
    int qt = t & (NT - 1);
    float m = g_repm[t], l = g_repl[t];
    float sc[NT];
    #pragma unroll
    for (int kt = 0; kt < NT; kt++)
        sc[kt] = (kt <= qt) ? expf(g_tile[(size_t)t * NT + kt] - m) / l : 0.0f;
    float* dst = out + (size_t)SQ * EMB + (size_t)t * TPK;
    for (int r = 0; r < TPK; r++) {
        float bv = -1e38f; int bi = 0;
        #pragma unroll
        for (int kt = 0; kt < NT; kt++)
            if (sc[kt] > bv) { bv = sc[kt]; bi = kt; }
        sc[bi] = -1e38f;
        dst[r] = (float)bi;
    }
}

// ---------------- launch ----------------------------------------------------
extern "C" void kernel_launch(void* const* d_in, const int* in_sizes, int n_in,
                              void* d_out, int out_size) {
    const float* x    = (const float*)d_in[0];
    const float* wq   = (const float*)d_in[1];
    const float* wk   = (const float*)d_in[2];
    const float* wv   = (const float*)d_in[3];
    const float* wo   = (const float*)d_in[4];
    const float* cosb = (const float*)d_in[5];
    const float* sinb = (const float*)d_in[6];
    float* out = (float*)d_out;

    void *pxh, *pxl, *pwth, *pwtl, *pah, *pal;
    cudaGetSymbolAddress(&pxh, g_xh);
    cudaGetSymbolAddress(&pxl, g_xl);
    cudaGetSymbolAddress(&pwth, g_wth);
    cudaGetSymbolAddress(&pwtl, g_wtl);
    cudaGetSymbolAddress(&pah, g_ah);
    cudaGetSymbolAddress(&pal, g_al);
    __half* xh = (__half*)pxh;
    __half* xl = (__half*)pxl;
    __half* wth = (__half*)pwth;
    __half* wtl = (__half*)pwtl;
    __half* ah = (__half*)pah;
    __half* al = (__half*)pal;

    cudaFuncSetAttribute(gemm_tc, cudaFuncAttributeMaxDynamicSharedMemorySize, G_SMEM);
    cudaFuncSetAttribute(attn_tc, cudaFuncAttributeMaxDynamicSharedMemorySize, ATT_SMEM);

    const size_t WSZ = (size_t)EMB * EMB;

    split_kernel<<<(SQ * EMB + 255) / 256, 256>>>(x, xh, xl, SQ * EMB);
    wprep_kernel<<<dim3(32, 32, 4), dim3(32, 8)>>>(wq, wk, wv, wo, wth, wtl);

    // combined QKV (z = 0,1,2); rope fused into z=0/1 epilogue
    gemm_tc<<<dim3(EMB / 128, SQ / 128, 3), 256, G_SMEM>>>(
        xh, xl, wth, wtl, cosb, sinb, nullptr, 3);

    attn_tc<<<dim3(NT, NH), 256, ATT_SMEM>>>(ah, al);

    gemm_tc<<<dim3(EMB / 128, SQ / 128), 256, G_SMEM>>>(
        ah, al, wth + 3 * WSZ, wtl + 3 * WSZ, nullptr, nullptr, out, 0);

    if (out_size >= SQ * EMB + NH * NT * TPK)
        topk_kernel<<<1, 256>>>(out);
}

// round 17
// speedup vs baseline: 1.5060x; 1.0270x over previous
#include <cuda_runtime.h>
#include <cuda_bf16.h>
#include <cuda_fp16.h>
#include <stdint.h>
#include <math.h>

#define SQ   4096
#define NH   8
#define HD   128
#define EMB  1024
#define NT   32
#define TPK  8
#define NEGV (-1e10f)

// ---------------- scratch (static device globals; no allocs allowed) --------
__device__ float g_tile[NH * NT * NT];
__device__ float g_repm[NH * NT];
__device__ float g_repl[NH * NT];
__device__ __half g_xh[SQ * EMB];
__device__ __half g_xl[SQ * EMB];
__device__ __half g_wth[4 * EMB * EMB];   // [w][n][k] transposed, fp16 hi
__device__ __half g_wtl[4 * EMB * EMB];   // fp16 lo (used only for wq,wk)
__device__ __half g_ah[SQ * EMB];
__device__ __nv_bfloat16 g_qh[NH * SQ * HD];
__device__ __nv_bfloat16 g_ql[NH * SQ * HD];
__device__ __nv_bfloat16 g_kh[NH * SQ * HD];
__device__ __nv_bfloat16 g_kl[NH * SQ * HD];
__device__ __half g_vh[NH * SQ * HD];

// ======================= helpers ===========================================
__device__ __forceinline__ uint32_t smem_u32(const void* p) {
    uint32_t a;
    asm("{ .reg .u64 t; cvta.to.shared.u64 t, %1; cvt.u32.u64 %0, t; }"
        : "=r"(a) : "l"(p));
    return a;
}
#define SWZ64(o)  ((o) ^ (((o) >> 3) & 0x30))   // 64B rows
#define SWZ256(o) ((o) ^ (((o) >> 4) & 0x70))   // 256B rows

__device__ __forceinline__ void cp16(uint32_t dst, const void* src) {
    asm volatile("cp.async.cg.shared.global [%0], [%1], 16;"
                 :: "r"(dst), "l"(src));
}
__device__ __forceinline__ void cp_commit() {
    asm volatile("cp.async.commit_group;" ::: "memory");
}
__device__ __forceinline__ void cp_wait1() {
    asm volatile("cp.async.wait_group 1;" ::: "memory");
}
__device__ __forceinline__ void cp_wait0() {
    asm volatile("cp.async.wait_group 0;" ::: "memory");
}
__device__ __forceinline__ void ldmx4(uint32_t* r, uint32_t addr) {
    asm volatile("ldmatrix.sync.aligned.m8n8.x4.shared.b16 {%0,%1,%2,%3}, [%4];"
        : "=r"(r[0]), "=r"(r[1]), "=r"(r[2]), "=r"(r[3]) : "r"(addr));
}
__device__ __forceinline__ void ldmx4t(uint32_t* r, uint32_t addr) {
    asm volatile("ldmatrix.sync.aligned.m8n8.x4.trans.shared.b16 {%0,%1,%2,%3}, [%4];"
        : "=r"(r[0]), "=r"(r[1]), "=r"(r[2]), "=r"(r[3]) : "r"(addr));
}
__device__ __forceinline__ void mma16816(float* c, const uint32_t* a,
                                         const uint32_t* b) {
    asm volatile(
        "mma.sync.aligned.m16n8k16.row.col.f32.bf16.bf16.f32 "
        "{%0,%1,%2,%3}, {%4,%5,%6,%7}, {%8,%9}, {%0,%1,%2,%3};"
        : "+f"(c[0]), "+f"(c[1]), "+f"(c[2]), "+f"(c[3])
        : "r"(a[0]), "r"(a[1]), "r"(a[2]), "r"(a[3]), "r"(b[0]), "r"(b[1]));
}
__device__ __forceinline__ void mma16816h(float* c, const uint32_t* a,
                                          const uint32_t* b) {
    asm volatile(
        "mma.sync.aligned.m16n8k16.row.col.f32.f16.f16.f32 "
        "{%0,%1,%2,%3}, {%4,%5,%6,%7}, {%8,%9}, {%0,%1,%2,%3};"
        : "+f"(c[0]), "+f"(c[1]), "+f"(c[2]), "+f"(c[3])
        : "r"(a[0]), "r"(a[1]), "r"(a[2]), "r"(a[3]), "r"(b[0]), "r"(b[1]));
}
__device__ __forceinline__ uint32_t hpack(float lo, float hi) {
    __half2 v = __floats2half2_rn(lo, hi);
    return *reinterpret_cast<uint32_t*>(&v);
}

// ======================= prep kernels =======================================
__global__ void split_kernel(const float* __restrict__ in,
                             __half* __restrict__ hi,
                             __half* __restrict__ lo, int n) {
    int i = blockIdx.x * blockDim.x + threadIdx.x;
    if (i >= n) return;
    float x = in[i];
    __half h = __float2half_rn(x);
    hi[i] = h;
    lo[i] = __float2half_rn(x - __half2float(h));
}

__global__ void wprep_kernel(const float* __restrict__ w0, const float* __restrict__ w1,
                             const float* __restrict__ w2, const float* __restrict__ w3,
                             __half* __restrict__ hi, __half* __restrict__ lo) {
    __shared__ float t[32][33];
    const float* w = (blockIdx.z == 0) ? w0 : (blockIdx.z == 1) ? w1
                    : (blockIdx.z == 2) ? w2 : w3;
    int k0 = blockIdx.x * 32, n0 = blockIdx.y * 32;
    int tx = threadIdx.x, ty = threadIdx.y;
    for (int r = ty; r < 32; r += 8)
        t[r][tx] = w[(size_t)(k0 + r) * EMB + n0 + tx];
    __syncthreads();
    size_t base = (size_t)blockIdx.z * EMB * EMB;
    for (int r = ty; r < 32; r += 8) {
        float x = t[tx][r];
        __half h = __float2half_rn(x);
        size_t o = base + (size_t)(n0 + r) * EMB + k0 + tx;
        hi[o] = h;
        lo[o] = __float2half_rn(x - __half2float(h));
    }
}

// ======= HMMA GEMM (3-stage cp.async, single barrier per chunk, BK=32) ======
// modes: 0 = fp32 row-major out (1-term Ah*Bh);
//        3 = combined QKV: z=0 q (3-term, rope+split fused),
//            z=1 k (3-term, rope+split fused), z=2 v (1-term, fp16 head-major)
#define G_STAGE 32768
#define G_SMEM  (3 * G_STAGE)

__global__ __launch_bounds__(256, 2) void gemm_tc(
    const __half* __restrict__ Ah, const __half* __restrict__ Al,
    const __half* __restrict__ Bh, const __half* __restrict__ Bl,
    const float* __restrict__ cosb, const float* __restrict__ sinb,
    float* __restrict__ C, int mode) {
    extern __shared__ __align__(1024) char smem[];
    uint32_t sb = smem_u32(smem);

    int tid = threadIdx.x, wid = tid >> 5, lid = tid & 31;
    int wm = wid & 3, wn = wid >> 2;
    int bm = blockIdx.y * 128, bn = blockIdx.x * 128;
    bool t3 = false;        // 3-term? (else 1-term Ah*Bh)
    if (mode == 3) {
        size_t zofs = (size_t)blockIdx.z * EMB * EMB;
        Bh += zofs; Bl += zofs;
        t3 = (blockIdx.z < 2);
    }

    float acc[2][8][4];
    #pragma unroll
    for (int i = 0; i < 2; i++)
        #pragma unroll
        for (int j = 0; j < 8; j++)
            #pragma unroll
            for (int kq = 0; kq < 4; kq++) acc[i][j][kq] = 0.0f;

    uint32_t a_row0 = (uint32_t)(wm * 32 + (lid & 15));
    uint32_t a_kb   = (uint32_t)((lid >> 4) * 16);
    uint32_t b_row  = (uint32_t)(wn * 64 + ((lid >> 4) << 3) + (lid & 7));
    uint32_t b_half = (uint32_t)(((lid >> 3) & 1) * 16);

    auto issue = [&](int c, int stg) {
        uint32_t base = sb + stg * G_STAGE;
        #pragma unroll
        for (int it = 0; it < 2; it++) {
            int i = tid + it * 256;
            int r = i >> 2, u = i & 3;
            uint32_t so = SWZ64((uint32_t)(r * 64 + u * 16));
            size_t ga = (size_t)(bm + r) * EMB + c * 32 + u * 8;
            size_t gb = (size_t)(bn + r) * EMB + c * 32 + u * 8;
            cp16(base + so,          Ah + ga);
            cp16(base + 16384 + so,  Bh + gb);
            if (t3) {
                cp16(base + 8192 + so,  Al + ga);
                cp16(base + 24576 + so, Bl + gb);
            }
        }
    };

    issue(0, 0); cp_commit();
    issue(1, 1); cp_commit();

    int stg = 0;
    for (int c = 0; c < 32; c++) {
        cp_wait1();
        __syncthreads();               // single barrier per chunk
        if (c + 2 < 32) issue(c + 2, (stg + 2) % 3);
        cp_commit();
        uint32_t saH = sb + stg * G_STAGE;
        uint32_t saL = saH + 8192;
        uint32_t sbH = saH + 16384;
        uint32_t sbL = saH + 24576;
        #pragma unroll
        for (int ks = 0; ks < 2; ks++) {
            uint32_t kofs = (uint32_t)(ks * 32);
            uint32_t aH[2][4], aL[2][4];
            uint32_t o0 = SWZ64(a_row0 * 64 + kofs + a_kb);
            uint32_t o1 = SWZ64((a_row0 + 16) * 64 + kofs + a_kb);
            ldmx4(aH[0], saH + o0);
            ldmx4(aH[1], saH + o1);
            if (t3) {
                ldmx4(aL[0], saL + o0);
                ldmx4(aL[1], saL + o1);
            }
            #pragma unroll
            for (int pg = 0; pg < 4; pg++) {
                uint32_t bo = SWZ64((b_row + pg * 16) * 64 + kofs + b_half);
                uint32_t bH[4], bL[4];
                ldmx4(bH, sbH + bo);
                if (t3) ldmx4(bL, sbL + bo);
                #pragma unroll
                for (int mt = 0; mt < 2; mt++)
                    #pragma unroll
                    for (int nt = 0; nt < 2; nt++) {
                        float* cc = acc[mt][pg * 2 + nt];
                        mma16816h(cc, aH[mt], bH + nt * 2);
                        if (t3) {
                            mma16816h(cc, aH[mt], bL + nt * 2);
                            mma16816h(cc, aL[mt], bH + nt * 2);
                        }
                    }
            }
        }
        stg = (stg == 2) ? 0 : stg + 1;
    }

    int gr = lid >> 2, gc = (lid & 3) * 2;
    int z = (mode == 3) ? blockIdx.z : -1;

    if (z == 0 || z == 1) {
        // ---- fused rope + bf16 split epilogue (pairs d, d+64 are CTA-local) --
        cp_wait0();
        __syncthreads();
        float* Cst = (float*)smem;            // 128 x 129 fp32 = 66048 B
        #pragma unroll
        for (int mt = 0; mt < 2; mt++) {
            int r0 = wm * 32 + mt * 16 + gr;
            #pragma unroll
            for (int nt = 0; nt < 8; nt++) {
                int col = wn * 64 + nt * 8 + gc;
                Cst[r0 * 129 + col]           = acc[mt][nt][0];
                Cst[r0 * 129 + col + 1]       = acc[mt][nt][1];
                Cst[(r0 + 8) * 129 + col]     = acc[mt][nt][2];
                Cst[(r0 + 8) * 129 + col + 1] = acc[mt][nt][3];
            }
        }
        __syncthreads();
        int head = blockIdx.x;
        const float sc = (z == 0) ? 0.08838834764831845f : 1.0f;
        __nv_bfloat16* oh = (z == 0) ? g_qh : g_kh;
        __nv_bfloat16* ol = (z == 0) ? g_ql : g_kl;
        for (int i = tid; i < 8192; i += 256) {
            int r = i >> 6, d = i & 63;
            float cv = cosb[(bm + r) * 64 + d];
            float sv = sinb[(bm + r) * 64 + d];
            float a = Cst[r * 129 + d];
            float b = Cst[r * 129 + d + 64];
            float y0 = (a * cv - b * sv) * sc;
            float y1 = (b * cv + a * sv) * sc;
            size_t base = ((size_t)head * SQ + bm + r) * 128;
            __nv_bfloat16 t0 = __float2bfloat16(y0);
            __nv_bfloat16 t1 = __float2bfloat16(y1);
            oh[base + d]      = t0;
            ol[base + d]      = __float2bfloat16(y0 - __bfloat162float(t0));
            oh[base + d + 64] = t1;
            ol[base + d + 64] = __float2bfloat16(y1 - __bfloat162float(t1));
        }
        return;
    }

    #pragma unroll
    for (int mt = 0; mt < 2; mt++) {
        int row0 = bm + wm * 32 + mt * 16 + gr;
        #pragma unroll
        for (int nt = 0; nt < 8; nt++) {
            int col = wn * 64 + nt * 8 + gc;
            float v0 = acc[mt][nt][0], v1 = acc[mt][nt][1];
            float v2 = acc[mt][nt][2], v3 = acc[mt][nt][3];
            if (mode == 0) {
                *(float2*)&C[(size_t)row0 * EMB + bn + col] = make_float2(v0, v1);
                *(float2*)&C[(size_t)(row0 + 8) * EMB + bn + col] = make_float2(v2, v3);
            } else {   // z == 2 : v fp16 single, head-major
                size_t hb = ((size_t)(bn >> 7) * SQ) * 128;
                *(uint32_t*)&g_vh[hb + (size_t)row0 * 128 + col] = hpack(v0, v1);
                *(uint32_t*)&g_vh[hb + (size_t)(row0 + 8) * 128 + col] = hpack(v2, v3);
            }
        }
    }
}

// ============ tensor-core flash attention, BQ=128, BK=64, 3-stage KV ========
// QK: bf16 3-term (index-critical). PV: fp16 1-term. Single barrier per iter.
#define A_STAGE 49152
#define ATT_SMEM (65536 + 3 * A_STAGE + 128)

__global__ __launch_bounds__(256, 1) void attn_tc(__half* __restrict__ ah) {
    extern __shared__ __align__(1024) char sm[];
    char* sQh = sm;                 // 32KB Qh + 32KB Ql, 256B rows
    char* sQl = sm + 32768;
    float* tmax_s = (float*)(sm + 65536 + 3 * A_STAGE);
    uint32_t uQh = smem_u32(sQh), uQl = smem_u32(sQl);
    uint32_t uKV = smem_u32(sm + 65536);   // stage base

    int qb = (NT - 1) - blockIdx.x;
    int h = blockIdx.y;
    int tid = threadIdx.x, wid = tid >> 5, lid = tid & 31;
    int gr = lid >> 2, qc = lid & 3;

    {
        const __nv_bfloat16* qh = g_qh + ((size_t)h * SQ + qb * 128) * 128;
        const __nv_bfloat16* ql = g_ql + ((size_t)h * SQ + qb * 128) * 128;
        for (int i = tid; i < 2048; i += 256) {
            int r = i >> 4, ch = i & 15;
            uint32_t so = SWZ256((uint32_t)(r * 256 + ch * 16));
            *(uint4*)(sQh + so) = *(const uint4*)(qh + r * 128 + ch * 8);
            *(uint4*)(sQl + so) = *(const uint4*)(ql + r * 128 + ch * 8);
        }
    }
    if (tid < 32) tmax_s[tid] = -1e30f;

    float o[16][4];
    #pragma unroll
    for (int j = 0; j < 16; j++)
        #pragma unroll
        for (int i = 0; i < 4; i++) o[j][i] = 0.0f;
    float m0 = -1e30f, m1 = -1e30f, l0 = 0.0f, l1 = 0.0f;

    int row0 = qb * 128 + wid * 16 + gr;
    int row1 = row0 + 8;

    uint32_t qa_row = (uint32_t)(wid * 16 + (lid & 15));
    uint32_t qa_kb  = (uint32_t)((lid >> 4) * 16);
    uint32_t kb_row = (uint32_t)(((lid >> 4) << 3) + (lid & 7));
    uint32_t kb_hf  = (uint32_t)(((lid >> 3) & 1) * 16);
    uint32_t v_row  = (uint32_t)(((lid >> 3) & 1) * 8 + (lid & 7));
    uint32_t v_col  = (uint32_t)((lid >> 4) << 4);

    int nkb = 2 * qb + 2;

    auto issue = [&](int kb, int stg) {
        uint32_t base = uKV + stg * A_STAGE;
        size_t gb = ((size_t)h * SQ + kb * 64) * 128;
        #pragma unroll
        for (int it = 0; it < 4; it++) {
            int i = tid + it * 256;
            int r = i >> 4, u = i & 15;
            uint32_t so = SWZ256((uint32_t)(r * 256 + u * 16));
            size_t go = gb + r * 128 + u * 8;
            cp16(base + so,          g_kh + go);
            cp16(base + 16384 + so,  g_kl + go);
            cp16(base + 32768 + so,  g_vh + go);
        }
    };

    issue(0, 0); cp_commit();
    issue(1, 1); cp_commit();

    int stg = 0;
    for (int kb = 0; kb < nkb; kb++) {
        cp_wait1();
        __syncthreads();               // single barrier per iteration
        if (kb + 2 < nkb) issue(kb + 2, (stg + 2) % 3);
        cp_commit();
        uint32_t uKh = uKV + stg * A_STAGE;
        uint32_t uKl = uKh + 16384;
        uint32_t uVh = uKh + 32768;

        // ---- S = Q K^T (bf16 3-term, index-critical) ----
        float s[8][4];
        #pragma unroll
        for (int j = 0; j < 8; j++)
            #pragma unroll
            for (int i = 0; i < 4; i++) s[j][i] = 0.0f;

        #pragma unroll
        for (int dc = 0; dc < 8; dc++) {
            uint32_t qo = SWZ256(qa_row * 256 + (uint32_t)(dc * 32) + qa_kb);
            uint32_t aH[4], aL[4];
            ldmx4(aH, uQh + qo);
            ldmx4(aL, uQl + qo);
            #pragma unroll
            for (int nf = 0; nf < 4; nf++) {
                uint32_t ko = SWZ256((kb_row + nf * 16) * 256 + (uint32_t)(dc * 32) + kb_hf);
                uint32_t bH[4], bL[4];
                ldmx4(bH, uKh + ko);
                ldmx4(bL, uKl + ko);
                #pragma unroll
                for (int nt = 0; nt < 2; nt++) {
                    float* cc = s[nf * 2 + nt];
                    mma16816(cc, aH, bH + nt * 2);
                    mma16816(cc, aH, bL + nt * 2);
                    mma16816(cc, aL, bH + nt * 2);
                }
            }
        }
        if (kb >= 2 * qb) {
            #pragma unroll
            for (int j = 0; j < 8; j++) {
                int colb = kb * 64 + j * 8 + 2 * qc;
                if (colb > row0)     s[j][0] = NEGV;
                if (colb + 1 > row0) s[j][1] = NEGV;
                if (colb > row1)     s[j][2] = NEGV;
                if (colb + 1 > row1) s[j][3] = NEGV;
            }
        }
        float tm0 = -1e30f, tm1 = -1e30f;
        #pragma unroll
        for (int j = 0; j < 8; j++) {
            tm0 = fmaxf(tm0, fmaxf(s[j][0], s[j][1]));
            tm1 = fmaxf(tm1, fmaxf(s[j][2], s[j][3]));
        }
        tm0 = fmaxf(tm0, __shfl_xor_sync(0xffffffffu, tm0, 1));
        tm0 = fmaxf(tm0, __shfl_xor_sync(0xffffffffu, tm0, 2));
        tm1 = fmaxf(tm1, __shfl_xor_sync(0xffffffffu, tm1, 1));
        tm1 = fmaxf(tm1, __shfl_xor_sync(0xffffffffu, tm1, 2));
        if (wid == 7 && lid == 28)
            tmax_s[kb >> 1] = fmaxf(tmax_s[kb >> 1], tm1);
        float mn0 = fmaxf(m0, tm0), mn1 = fmaxf(m1, tm1);
        float al0 = __expf(m0 - mn0), al1 = __expf(m1 - mn1);
        m0 = mn0; m1 = mn1;
        #pragma unroll
        for (int j = 0; j < 16; j++) {
            o[j][0] *= al0; o[j][1] *= al0;
            o[j][2] *= al1; o[j][3] *= al1;
        }
        float rs0 = 0.0f, rs1 = 0.0f;
        // ---- P (fp16, single) fed into 1-term fp16 PV ----
        #pragma unroll
        for (int t = 0; t < 4; t++) {
            uint32_t pH[4];
            #pragma unroll
            for (int jj = 0; jj < 2; jj++) {
                int j = 2 * t + jj;
                float e0 = __expf(s[j][0] - m0);
                float e1 = __expf(s[j][1] - m0);
                float e2 = __expf(s[j][2] - m1);
                float e3 = __expf(s[j][3] - m1);
                rs0 += e0 + e1; rs1 += e2 + e3;
                pH[2 * jj]     = hpack(e0, e1);
                pH[2 * jj + 1] = hpack(e2, e3);
            }
            #pragma unroll
            for (int nf = 0; nf < 8; nf++) {
                uint32_t vo = SWZ256((uint32_t)((t * 16 + v_row) * 256 + nf * 32) + v_col);
                uint32_t vH[4];
                ldmx4t(vH, uVh + vo);
                #pragma unroll
                for (int nt = 0; nt < 2; nt++)
                    mma16816h(o[nf * 2 + nt], pH, vH + nt * 2);
            }
        }
        rs0 += __shfl_xor_sync(0xffffffffu, rs0, 1);
        rs0 += __shfl_xor_sync(0xffffffffu, rs0, 2);
        rs1 += __shfl_xor_sync(0xffffffffu, rs1, 1);
        rs1 += __shfl_xor_sync(0xffffffffu, rs1, 2);
        l0 = l0 * al0 + rs0;
        l1 = l1 * al1 + rs1;

        stg = (stg == 2) ? 0 : stg + 1;
    }

    // ---- epilogue: normalize, fp16 (hi only; out-GEMM is 1-term) ----
    float inv0 = 1.0f / l0, inv1 = 1.0f / l1;
    #pragma unroll
    for (int j = 0; j < 16; j++) {
        int col = h * 128 + j * 8 + 2 * qc;
        float v0 = o[j][0] * inv0, v1 = o[j][1] * inv0;
        float v2 = o[j][2] * inv1, v3 = o[j][3] * inv1;
        *(uint32_t*)&ah[(size_t)row0 * EMB + col] = hpack(v0, v1);
        *(uint32_t*)&ah[(size_t)row1 * EMB + col] = hpack(v2, v3);
    }
    if (wid == 7 && lid == 28) {
        g_repm[h * NT + qb] = m1;
        g_repl[h * NT + qb] = l1;
    }
    __syncthreads();
    if (tid < 32)
        g_tile[((size_t)h * NT + qb) * NT + tid] = tmax_s[tid];
}

// ---------------- anchor tile scores + top-8 --------------------------------
__global__ void topk_kernel(float* __restrict__ out) {
    int t = blockIdx.x * blockDim.x + threadIdx.x;
    if (t >= NH * NT) return;
    int qt = t & (NT - 1);
    float m = g_repm[t], l = g_repl[t];
    float sc[NT];
    #pragma unroll
    for (int kt = 0; kt < NT; kt++)
        sc[kt] = (kt <= qt) ? expf(g_tile[(size_t)t * NT + kt] - m) / l : 0.0f;
    float* dst = out + (size_t)SQ * EMB + (size_t)t * TPK;
    for (int r = 0; r < TPK; r++) {
        float bv = -1e38f; int bi = 0;
        #pragma unroll
        for (int kt = 0; kt < NT; kt++)
            if (sc[kt] > bv) { bv = sc[kt]; bi = kt; }
        sc[bi] = -1e38f;
        dst[r] = (float)bi;
    }
}

// ---------------- launch ----------------------------------------------------
extern "C" void kernel_launch(void* const* d_in, const int* in_sizes, int n_in,
                              void* d_out, int out_size) {
    const float* x    = (const float*)d_in[0];
    const float* wq   = (const float*)d_in[1];
    const float* wk   = (const float*)d_in[2];
    const float* wv   = (const float*)d_in[3];
    const float* wo   = (const float*)d_in[4];
    const float* cosb = (const float*)d_in[5];
    const float* sinb = (const float*)d_in[6];
    float* out = (float*)d_out;

    void *pxh, *pxl, *pwth, *pwtl, *pah;
    cudaGetSymbolAddress(&pxh, g_xh);
    cudaGetSymbolAddress(&pxl, g_xl);
    cudaGetSymbolAddress(&pwth, g_wth);
    cudaGetSymbolAddress(&pwtl, g_wtl);
    cudaGetSymbolAddress(&pah, g_ah);
    __half* xh = (__half*)pxh;
    __half* xl = (__half*)pxl;
    __half* wth = (__half*)pwth;
    __half* wtl = (__half*)pwtl;
    __half* ah = (__half*)pah;

    cudaFuncSetAttribute(gemm_tc, cudaFuncAttributeMaxDynamicSharedMemorySize, G_SMEM);
    cudaFuncSetAttribute(attn_tc, cudaFuncAttributeMaxDynamicSharedMemorySize, ATT_SMEM);

    const size_t WSZ = (size_t)EMB * EMB;

    split_kernel<<<(SQ * EMB + 255) / 256, 256>>>(x, xh, xl, SQ * EMB);
    wprep_kernel<<<dim3(32, 32, 4), dim3(32, 8)>>>(wq, wk, wv, wo, wth, wtl);

    // combined QKV (z = 0,1,2); rope fused into z=0/1 epilogue
    gemm_tc<<<dim3(EMB / 128, SQ / 128, 3), 256, G_SMEM>>>(
        xh, xl, wth, wtl, cosb, sinb, nullptr, 3);

    attn_tc<<<dim3(NT, NH), 256, ATT_SMEM>>>(ah);

    gemm_tc<<<dim3(EMB / 128, SQ / 128), 256, G_SMEM>>>(
        ah, ah, wth + 3 * WSZ, wtl + 3 * WSZ, nullptr, nullptr, out, 0);

    if (out_size >= SQ * EMB + NH * NT * TPK)
        topk_kernel<<<1, 256>>>(out);
}